// round 16
// baseline (speedup 1.0000x reference)
#include <cuda_runtime.h>
#include <cstdint>

#define S_LEN 2048
#define NHEADS 16
#define DKV 64
#define HID 1024
#define BATCH 4
#define MROWS (BATCH*S_LEN)   // 8192

// Scratch (allocation-free rule: __device__ globals)
__device__ float g_q[BATCH*NHEADS*S_LEN*DKV];   // 32MB each
__device__ float g_k[BATCH*NHEADS*S_LEN*DKV];
__device__ float g_v[BATCH*NHEADS*S_LEN*DKV];
__device__ float g_ctx[MROWS*HID];

// ---------------- helpers ----------------
__device__ __forceinline__ void cp_async16(void* sdst, const void* gsrc){
    unsigned s = (unsigned)__cvta_generic_to_shared(sdst);
    asm volatile("cp.async.cg.shared.global [%0], [%1], 16;\n" :: "r"(s), "l"(gsrc));
}
__device__ __forceinline__ void cp_commit(){ asm volatile("cp.async.commit_group;\n"); }
template<int N> __device__ __forceinline__ void cp_wait(){ asm volatile("cp.async.wait_group %0;\n" :: "n"(N)); }

__device__ __forceinline__ unsigned f2tf(float x){
    unsigned r; asm("cvt.rna.tf32.f32 %0, %1;\n" : "=r"(r) : "f"(x)); return r;
}
__device__ __forceinline__ float ex2(float x){
    float y; asm("ex2.approx.ftz.f32 %0, %1;\n" : "=f"(y) : "f"(x)); return y;
}
__device__ __forceinline__ void mma_tf32(float c[4], const unsigned a[4], unsigned b0, unsigned b1){
    asm volatile("mma.sync.aligned.m16n8k8.row.col.f32.tf32.tf32.f32 "
        "{%0,%1,%2,%3},{%4,%5,%6,%7},{%8,%9},{%0,%1,%2,%3};\n"
        : "+f"(c[0]), "+f"(c[1]), "+f"(c[2]), "+f"(c[3])
        : "r"(a[0]), "r"(a[1]), "r"(a[2]), "r"(a[3]), "r"(b0), "r"(b1));
}

// ---------------- GEMM: C[M,N] = A[M,K] @ B[K,N] + bias ----------------
// Block 128x128, K-tile 32, 8 warps (4 along M x 2 along N), warp tile 32x64.
// MODE 0: scatter epilogue into Q/K/V [b,h,s,d].  MODE 1: plain row-major store.
#define BM 128
#define BN 128
#define BKK 32
#define ASTR 36      // 36 mod 32 == 4 -> A-fragment LDS conflict-free
#define BSTR 136     // 136 mod 32 == 8 -> B-fragment LDS conflict-free
#define A_STAGE (BM*ASTR)     // 4608 floats
#define B_STAGE (BKK*BSTR)    // 4352 floats
#define GEMM_SMEM ((2*A_STAGE + 2*B_STAGE)*4)   // 71680 B

template<int MODE>
__global__ void __launch_bounds__(256,2) gemm_tf32(
    const float* __restrict__ A, const float* __restrict__ Bw,
    const float* __restrict__ bias, float* __restrict__ C,
    int N, int K,
    float* __restrict__ oq, float* __restrict__ ok, float* __restrict__ ov)
{
    extern __shared__ float sm[];
    float* As = sm;
    float* Bs = sm + 2*A_STAGE;
    const int tid = threadIdx.x, lane = tid & 31, warp = tid >> 5;
    const int wm = warp & 3, wn = warp >> 2;
    const int bm = blockIdx.y * BM, bn = blockIdx.x * BN;

    float acc[2][8][4];
    #pragma unroll
    for (int i=0;i<2;i++)
        #pragma unroll
        for (int j=0;j<8;j++)
            #pragma unroll
            for (int l=0;l<4;l++) acc[i][j][l]=0.f;

    auto loadA = [&](int st, int k0){
        float* dst = As + st*A_STAGE;
        const float* src = A + (size_t)bm*K + k0;
        #pragma unroll
        for (int i=0;i<4;i++){
            int idx = tid + 256*i;
            int r = idx >> 3, c = (idx & 7) << 2;   // 128 rows x 8 float4
            cp_async16(dst + r*ASTR + c, src + (size_t)r*K + c);
        }
    };
    auto loadB = [&](int st, int k0){
        float* dst = Bs + st*B_STAGE;
        const float* src = Bw + (size_t)k0*N + bn;
        #pragma unroll
        for (int i=0;i<4;i++){
            int idx = tid + 256*i;
            int r = idx >> 5, c = (idx & 31) << 2;  // 32 rows x 32 float4
            cp_async16(dst + r*BSTR + c, src + (size_t)r*N + c);
        }
    };

    loadA(0,0); loadB(0,0); cp_commit();
    const int nk = K / BKK;
    for (int kt=0; kt<nk; kt++){
        if (kt+1 < nk){ loadA((kt+1)&1, (kt+1)*BKK); loadB((kt+1)&1, (kt+1)*BKK); cp_commit(); cp_wait<1>(); }
        else            cp_wait<0>();
        __syncthreads();
        const float* as = As + (kt&1)*A_STAGE;
        const float* bs = Bs + (kt&1)*B_STAGE;
        #pragma unroll
        for (int ks=0; ks<4; ks++){
            const int kk = ks*8;
            unsigned af[2][4];
            #pragma unroll
            for (int mt=0; mt<2; mt++){
                int r = wm*32 + mt*16 + (lane>>2);
                const float* ap = as + r*ASTR + kk + (lane&3);
                af[mt][0] = f2tf(ap[0]);
                af[mt][1] = f2tf(ap[8*ASTR]);
                af[mt][2] = f2tf(ap[4]);
                af[mt][3] = f2tf(ap[8*ASTR+4]);
            }
            #pragma unroll
            for (int nt=0; nt<8; nt++){
                int n = wn*64 + nt*8 + (lane>>2);
                const float* bp = bs + (kk + (lane&3))*BSTR + n;
                unsigned b0 = f2tf(bp[0]);
                unsigned b1 = f2tf(bp[4*BSTR]);
                mma_tf32(acc[0][nt], af[0], b0, b1);
                mma_tf32(acc[1][nt], af[1], b0, b1);
            }
        }
        __syncthreads();
    }

    // epilogue
    #pragma unroll
    for (int nt=0; nt<8; nt++){
        const int c = bn + wn*64 + nt*8 + (lane&3)*2;
        const float bb0 = bias[c], bb1 = bias[c+1];
        #pragma unroll
        for (int mt=0; mt<2; mt++){
            const int r0 = bm + wm*32 + mt*16 + (lane>>2);
            const float v0 = acc[mt][nt][0] + bb0, v1 = acc[mt][nt][1] + bb1;
            const float v2 = acc[mt][nt][2] + bb0, v3 = acc[mt][nt][3] + bb1;
            if (MODE == 0){
                // col c -> (t, h, d); row -> (b, s); write [b,h,s,d]
                const int t = c >> 10, h = (c >> 6) & 15, d = c & 63;
                float* buf = (t==0) ? oq : ((t==1) ? ok : ov);
                const int bi = r0 >> 11, s0 = r0 & 2047;
                const size_t base = ((((size_t)bi*NHEADS + h)*S_LEN) + s0)*DKV + d;
                *reinterpret_cast<float2*>(buf + base)              = make_float2(v0, v1);
                *reinterpret_cast<float2*>(buf + base + 8*DKV)      = make_float2(v2, v3);
            } else {
                *reinterpret_cast<float2*>(C + (size_t)r0*N + c)        = make_float2(v0, v1);
                *reinterpret_cast<float2*>(C + (size_t)(r0+8)*N + c)    = make_float2(v2, v3);
            }
        }
    }
}

// ---------------- Flash attention (tf32 mma, online softmax in log2 domain) ----------------
// CTA = one (b,h) + 128 q rows. 8 warps, each owns 16 q rows. KV tiles of 64 rows, double-buffered.
#define PSTR 68     // 68 mod 32 == 4 -> P/Q A-fragment LDS conflict-free
#define KSTR 68     // K^T B-fragment pattern: row=lane>>2, col=lane&3 -> conflict-free
#define VSTR 72     // 72 mod 32 == 8 -> V B-fragment pattern: row=lane&3, col=lane>>2 -> conflict-free
#define PS_SZ (128*PSTR)   // 8704 floats
#define KS_SZ (64*KSTR)    // 4352
#define VS_SZ (64*VSTR)    // 4608
#define ATT_SMEM ((PS_SZ + 2*KS_SZ + 2*VS_SZ)*4)  // 106496 B

__global__ void __launch_bounds__(256,1) attn_tf32(
    const float* __restrict__ Q, const float* __restrict__ K,
    const float* __restrict__ V, float* __restrict__ ctx)
{
    extern __shared__ float sm[];
    float* Ps = sm;                 // Q staging, then P tile (warp-private rows)
    float* Ks = sm + PS_SZ;         // [2][64][KSTR]
    float* Vs = Ks + 2*KS_SZ;       // [2][64][VSTR]

    const int tid = threadIdx.x, lane = tid & 31, warp = tid >> 5;
    const int bh = blockIdx.y;                  // b*16 + h
    const int qb = blockIdx.x * 128;
    const float* Qp = Q + (size_t)bh*S_LEN*DKV;
    const float* Kp = K + (size_t)bh*S_LEN*DKV;
    const float* Vp = V + (size_t)bh*S_LEN*DKV;

    auto loadKV = [&](int st, int kb){
        float* kd = Ks + st*KS_SZ;
        float* vd = Vs + st*VS_SZ;
        #pragma unroll
        for (int i=0;i<4;i++){
            int idx = tid + 256*i;                 // 64 rows x 16 float4
            int r = idx >> 4, c = (idx & 15) << 2;
            cp_async16(kd + r*KSTR + c, Kp + (size_t)(kb+r)*DKV + c);
            cp_async16(vd + r*VSTR + c, Vp + (size_t)(kb+r)*DKV + c);
        }
    };

    // Stage Q tile into Ps
    #pragma unroll
    for (int i=0;i<8;i++){
        int idx = tid + 256*i;                     // 128 rows x 16 float4
        int r = idx >> 4, c = (idx & 15) << 2;
        cp_async16(Ps + r*PSTR + c, Qp + (size_t)(qb+r)*DKV + c);
    }
    cp_commit();
    loadKV(0, 0);
    cp_commit();
    cp_wait<1>();         // Q ready (KV0 still in flight)
    __syncthreads();

    // Q fragments, with softmax scale * log2(e) folded in (logits live in log2 domain)
    const float sc = 0.125f * 1.4426950408889634f;
    const int r0 = warp*16 + (lane>>2);
    unsigned qf[8][4];
    #pragma unroll
    for (int ks=0; ks<8; ks++){
        const float* p = Ps + r0*PSTR + ks*8 + (lane&3);
        qf[ks][0] = f2tf(p[0] * sc);
        qf[ks][1] = f2tf(p[8*PSTR] * sc);
        qf[ks][2] = f2tf(p[4] * sc);
        qf[ks][3] = f2tf(p[8*PSTR+4] * sc);
    }
    __syncthreads();  // everyone done with Q in Ps before reuse as P

    float o[8][4];
    #pragma unroll
    for (int i=0;i<8;i++)
        #pragma unroll
        for (int j=0;j<4;j++) o[i][j]=0.f;
    float m0 = -1e30f, m1 = -1e30f, l0 = 0.f, l1 = 0.f;

    for (int t=0; t<32; t++){
        if (t+1 < 32){ loadKV((t+1)&1, (t+1)*64); cp_commit(); cp_wait<1>(); }
        else           cp_wait<0>();
        __syncthreads();
        const float* ks_ = Ks + (t&1)*KS_SZ;
        const float* vs_ = Vs + (t&1)*VS_SZ;

        // S = (Q*sc) @ K^T  (B col-major = K row-major, contiguous in d)
        float s[8][4];
        #pragma unroll
        for (int i=0;i<8;i++)
            #pragma unroll
            for (int j=0;j<4;j++) s[i][j]=0.f;
        #pragma unroll
        for (int kp2=0; kp2<8; kp2++){
            #pragma unroll
            for (int nt=0; nt<8; nt++){
                const float* bp = ks_ + (nt*8 + (lane>>2))*KSTR + kp2*8 + (lane&3);
                unsigned b0 = f2tf(bp[0]);
                unsigned b1 = f2tf(bp[4]);
                mma_tf32(s[nt], qf[kp2], b0, b1);
            }
        }

        // online softmax (log2 domain)
        float mx0 = s[0][0], mx1 = s[0][2];
        #pragma unroll
        for (int nt=0; nt<8; nt++){
            mx0 = fmaxf(mx0, fmaxf(s[nt][0], s[nt][1]));
            mx1 = fmaxf(mx1, fmaxf(s[nt][2], s[nt][3]));
        }
        mx0 = fmaxf(mx0, __shfl_xor_sync(0xffffffffu, mx0, 1));
        mx0 = fmaxf(mx0, __shfl_xor_sync(0xffffffffu, mx0, 2));
        mx1 = fmaxf(mx1, __shfl_xor_sync(0xffffffffu, mx1, 1));
        mx1 = fmaxf(mx1, __shfl_xor_sync(0xffffffffu, mx1, 2));
        const float mn0 = fmaxf(m0, mx0), mn1 = fmaxf(m1, mx1);
        const float a0 = ex2(m0 - mn0),   a1 = ex2(m1 - mn1);
        float sum0 = 0.f, sum1 = 0.f;
        #pragma unroll
        for (int nt=0; nt<8; nt++){
            float p0 = ex2(s[nt][0]-mn0), p1 = ex2(s[nt][1]-mn0);
            float p2 = ex2(s[nt][2]-mn1), p3 = ex2(s[nt][3]-mn1);
            sum0 += p0 + p1; sum1 += p2 + p3;
            float* pw = Ps + r0*PSTR + nt*8 + (lane&3)*2;
            *reinterpret_cast<float2*>(pw)          = make_float2(p0, p1);
            *reinterpret_cast<float2*>(pw + 8*PSTR) = make_float2(p2, p3);
        }
        sum0 += __shfl_xor_sync(0xffffffffu, sum0, 1);
        sum0 += __shfl_xor_sync(0xffffffffu, sum0, 2);
        sum1 += __shfl_xor_sync(0xffffffffu, sum1, 1);
        sum1 += __shfl_xor_sync(0xffffffffu, sum1, 2);
        l0 = l0*a0 + sum0; l1 = l1*a1 + sum1;
        m0 = mn0; m1 = mn1;
        #pragma unroll
        for (int nt=0; nt<8; nt++){ o[nt][0]*=a0; o[nt][1]*=a0; o[nt][2]*=a1; o[nt][3]*=a1; }
        __syncwarp();   // P rows are warp-private; warp-level fence suffices

        // O += P @ V   (A from Ps, B col-major from Vs: stride VSTR over k)
        #pragma unroll
        for (int kp2=0; kp2<8; kp2++){
            unsigned pa[4];
            const float* pp = Ps + r0*PSTR + kp2*8 + (lane&3);
            pa[0] = f2tf(pp[0]);
            pa[1] = f2tf(pp[8*PSTR]);
            pa[2] = f2tf(pp[4]);
            pa[3] = f2tf(pp[8*PSTR+4]);
            #pragma unroll
            for (int nt=0; nt<8; nt++){
                const float* bp = vs_ + (kp2*8 + (lane&3))*VSTR + nt*8 + (lane>>2);
                unsigned b0 = f2tf(bp[0]);
                unsigned b1 = f2tf(bp[4*VSTR]);
                mma_tf32(o[nt], pa, b0, b1);
            }
        }
        __syncthreads();   // stage buffer reuse barrier
    }

    // normalize + write ctx[b, s, h*64+d]
    const float il0 = __fdividef(1.f, l0), il1 = __fdividef(1.f, l1);
    const int b = bh >> 4, h = bh & 15;
    const size_t row0 = ((size_t)b*S_LEN + qb + r0) * HID + h*DKV;
    #pragma unroll
    for (int nt=0; nt<8; nt++){
        const int c = nt*8 + (lane&3)*2;
        *reinterpret_cast<float2*>(ctx + row0 + c)           = make_float2(o[nt][0]*il0, o[nt][1]*il0);
        *reinterpret_cast<float2*>(ctx + row0 + 8*HID + c)   = make_float2(o[nt][2]*il1, o[nt][3]*il1);
    }
}

// ---------------- launch ----------------
extern "C" void kernel_launch(void* const* d_in, const int* in_sizes, int n_in,
                              void* d_out, int out_size)
{
    const float* x  = (const float*)d_in[0];
    const float* W1 = (const float*)d_in[1];
    const float* b1 = (const float*)d_in[2];
    const float* W2 = (const float*)d_in[3];
    const float* b2 = (const float*)d_in[4];
    float* out = (float*)d_out;

    float *qp, *kp, *vp, *cp;
    cudaGetSymbolAddress((void**)&qp, g_q);
    cudaGetSymbolAddress((void**)&kp, g_k);
    cudaGetSymbolAddress((void**)&vp, g_v);
    cudaGetSymbolAddress((void**)&cp, g_ctx);

    cudaFuncSetAttribute(gemm_tf32<0>, cudaFuncAttributeMaxDynamicSharedMemorySize, GEMM_SMEM);
    cudaFuncSetAttribute(gemm_tf32<1>, cudaFuncAttributeMaxDynamicSharedMemorySize, GEMM_SMEM);
    cudaFuncSetAttribute(attn_tf32,    cudaFuncAttributeMaxDynamicSharedMemorySize, ATT_SMEM);

    dim3 blk(256);
    // 1) QKV projection + scatter to [b,h,s,d]
    gemm_tf32<0><<<dim3(3*HID/BN, MROWS/BM), blk, GEMM_SMEM>>>(
        x, W1, b1, nullptr, 3*HID, HID, qp, kp, vp);
    // 2) flash attention -> ctx [b,s,h*d]
    attn_tf32<<<dim3(S_LEN/128, BATCH*NHEADS), blk, ATT_SMEM>>>(qp, kp, vp, cp);
    // 3) output projection
    gemm_tf32<1><<<dim3(HID/BN, MROWS/BM), blk, GEMM_SMEM>>>(
        cp, W2, b2, out, HID, HID, nullptr, nullptr, nullptr);
}

// round 17
// speedup vs baseline: 1.1227x; 1.1227x over previous
#include <cuda_runtime.h>
#include <cstdint>

#define S_LEN 2048
#define NHEADS 16
#define DKV 64
#define HID 1024
#define BATCH 4
#define MROWS (BATCH*S_LEN)   // 8192

// Scratch (allocation-free rule: __device__ globals)
__device__ float g_q[BATCH*NHEADS*S_LEN*DKV];
__device__ float g_k[BATCH*NHEADS*S_LEN*DKV];
__device__ float g_v[BATCH*NHEADS*S_LEN*DKV];
__device__ float g_ctx[MROWS*HID];
__device__ float g_x [MROWS*HID];          // tf32-rounded x
__device__ float g_w1[HID*3*NHEADS*DKV];   // tf32-rounded W1
__device__ float g_w2[NHEADS*DKV*HID];     // tf32-rounded W2

// ---------------- helpers ----------------
__device__ __forceinline__ void cp_async16(void* sdst, const void* gsrc){
    unsigned s = (unsigned)__cvta_generic_to_shared(sdst);
    asm volatile("cp.async.cg.shared.global [%0], [%1], 16;\n" :: "r"(s), "l"(gsrc));
}
__device__ __forceinline__ void cp_commit(){ asm volatile("cp.async.commit_group;\n"); }
template<int N> __device__ __forceinline__ void cp_wait(){ asm volatile("cp.async.wait_group %0;\n" :: "n"(N)); }

__device__ __forceinline__ unsigned f2tf(float x){
    unsigned r; asm("cvt.rna.tf32.f32 %0, %1;\n" : "=r"(r) : "f"(x)); return r;
}
__device__ __forceinline__ float rtf(float x){ return __uint_as_float(f2tf(x)); }
__device__ __forceinline__ float ex2(float x){
    float y; asm("ex2.approx.ftz.f32 %0, %1;\n" : "=f"(y) : "f"(x)); return y;
}
__device__ __forceinline__ void mma_tf32(float c[4], const unsigned a[4], unsigned b0, unsigned b1){
    asm volatile("mma.sync.aligned.m16n8k8.row.col.f32.tf32.tf32.f32 "
        "{%0,%1,%2,%3},{%4,%5,%6,%7},{%8,%9},{%0,%1,%2,%3};\n"
        : "+f"(c[0]), "+f"(c[1]), "+f"(c[2]), "+f"(c[3])
        : "r"(a[0]), "r"(a[1]), "r"(a[2]), "r"(a[3]), "r"(b0), "r"(b1));
}

// ---------------- prepass: tf32-round arrays ----------------
__global__ void round_tf32_kernel(const float* __restrict__ in, float* __restrict__ out, int n4){
    int i = blockIdx.x*blockDim.x + threadIdx.x;
    if (i < n4){
        float4 v = reinterpret_cast<const float4*>(in)[i];
        v.x = rtf(v.x); v.y = rtf(v.y); v.z = rtf(v.z); v.w = rtf(v.w);
        reinterpret_cast<float4*>(out)[i] = v;
    }
}

// ---------------- GEMM: C[M,N] = A[M,K] @ B[K,N] + bias ----------------
// Inputs A,B are pre-rounded to tf32; fragments are raw bit loads (no cvt in mainloop).
#define BM 128
#define BN 128
#define BKK 32
#define ASTR 36
#define BSTR 136
#define A_STAGE (BM*ASTR)
#define B_STAGE (BKK*BSTR)
#define GEMM_SMEM ((2*A_STAGE + 2*B_STAGE)*4)

template<int MODE>
__global__ void __launch_bounds__(256,2) gemm_tf32(
    const float* __restrict__ A, const float* __restrict__ Bw,
    const float* __restrict__ bias, float* __restrict__ C,
    int N, int K,
    float* __restrict__ oq, float* __restrict__ ok, float* __restrict__ ov)
{
    extern __shared__ float sm[];
    float* As = sm;
    float* Bs = sm + 2*A_STAGE;
    const int tid = threadIdx.x, lane = tid & 31, warp = tid >> 5;
    const int wm = warp & 3, wn = warp >> 2;
    const int bm = blockIdx.y * BM, bn = blockIdx.x * BN;

    float acc[2][8][4];
    #pragma unroll
    for (int i=0;i<2;i++)
        #pragma unroll
        for (int j=0;j<8;j++)
            #pragma unroll
            for (int l=0;l<4;l++) acc[i][j][l]=0.f;

    auto loadA = [&](int st, int k0){
        float* dst = As + st*A_STAGE;
        const float* src = A + (size_t)bm*K + k0;
        #pragma unroll
        for (int i=0;i<4;i++){
            int idx = tid + 256*i;
            int r = idx >> 3, c = (idx & 7) << 2;
            cp_async16(dst + r*ASTR + c, src + (size_t)r*K + c);
        }
    };
    auto loadB = [&](int st, int k0){
        float* dst = Bs + st*B_STAGE;
        const float* src = Bw + (size_t)k0*N + bn;
        #pragma unroll
        for (int i=0;i<4;i++){
            int idx = tid + 256*i;
            int r = idx >> 5, c = (idx & 31) << 2;
            cp_async16(dst + r*BSTR + c, src + (size_t)r*N + c);
        }
    };

    loadA(0,0); loadB(0,0); cp_commit();
    const int nk = K / BKK;
    for (int kt=0; kt<nk; kt++){
        if (kt+1 < nk){ loadA((kt+1)&1, (kt+1)*BKK); loadB((kt+1)&1, (kt+1)*BKK); cp_commit(); cp_wait<1>(); }
        else            cp_wait<0>();
        __syncthreads();
        const float* as = As + (kt&1)*A_STAGE;
        const float* bs = Bs + (kt&1)*B_STAGE;
        #pragma unroll
        for (int ks=0; ks<4; ks++){
            const int kk = ks*8;
            unsigned af[2][4];
            #pragma unroll
            for (int mt=0; mt<2; mt++){
                int r = wm*32 + mt*16 + (lane>>2);
                const float* ap = as + r*ASTR + kk + (lane&3);
                af[mt][0] = __float_as_uint(ap[0]);
                af[mt][1] = __float_as_uint(ap[8*ASTR]);
                af[mt][2] = __float_as_uint(ap[4]);
                af[mt][3] = __float_as_uint(ap[8*ASTR+4]);
            }
            #pragma unroll
            for (int nt=0; nt<8; nt++){
                int n = wn*64 + nt*8 + (lane>>2);
                const float* bp = bs + (kk + (lane&3))*BSTR + n;
                unsigned b0 = __float_as_uint(bp[0]);
                unsigned b1 = __float_as_uint(bp[4*BSTR]);
                mma_tf32(acc[0][nt], af[0], b0, b1);
                mma_tf32(acc[1][nt], af[1], b0, b1);
            }
        }
        __syncthreads();
    }

    // epilogue
    #pragma unroll
    for (int nt=0; nt<8; nt++){
        const int c = bn + wn*64 + nt*8 + (lane&3)*2;
        const float bb0 = bias[c], bb1 = bias[c+1];
        #pragma unroll
        for (int mt=0; mt<2; mt++){
            const int r0 = bm + wm*32 + mt*16 + (lane>>2);
            float v0 = acc[mt][nt][0] + bb0, v1 = acc[mt][nt][1] + bb1;
            float v2 = acc[mt][nt][2] + bb0, v3 = acc[mt][nt][3] + bb1;
            if (MODE == 0){
                // pre-round Q/K/V to tf32 so attention loads raw bits
                v0 = rtf(v0); v1 = rtf(v1); v2 = rtf(v2); v3 = rtf(v3);
                const int t = c >> 10, h = (c >> 6) & 15, d = c & 63;
                float* buf = (t==0) ? oq : ((t==1) ? ok : ov);
                const int bi = r0 >> 11, s0 = r0 & 2047;
                const size_t base = ((((size_t)bi*NHEADS + h)*S_LEN) + s0)*DKV + d;
                *reinterpret_cast<float2*>(buf + base)         = make_float2(v0, v1);
                *reinterpret_cast<float2*>(buf + base + 8*DKV) = make_float2(v2, v3);
            } else {
                *reinterpret_cast<float2*>(C + (size_t)r0*N + c)     = make_float2(v0, v1);
                *reinterpret_cast<float2*>(C + (size_t)(r0+8)*N + c) = make_float2(v2, v3);
            }
        }
    }
}

// ---------------- Flash attention (tf32 mma, online softmax in log2 domain) ----------------
// All mma operands pre-rounded; zero cvt on fragment loads. 2 CTAs/SM (4 warps/SMSP).
#define PSTR 68
#define KSTR 68
#define VSTR 72
#define PS_SZ (128*PSTR)
#define KS_SZ (64*KSTR)
#define VS_SZ (64*VSTR)
#define ATT_SMEM ((PS_SZ + 2*KS_SZ + 2*VS_SZ)*4)  // 106496 B -> 2 CTAs/SM fits 228KB

__global__ void __launch_bounds__(256,2) attn_tf32(
    const float* __restrict__ Q, const float* __restrict__ K,
    const float* __restrict__ V, float* __restrict__ ctx)
{
    extern __shared__ float sm[];
    float* Ps = sm;
    float* Ks = sm + PS_SZ;
    float* Vs = Ks + 2*KS_SZ;

    const int tid = threadIdx.x, lane = tid & 31, warp = tid >> 5;
    const int bh = blockIdx.y;
    const int qb = blockIdx.x * 128;
    const float* Qp = Q + (size_t)bh*S_LEN*DKV;
    const float* Kp = K + (size_t)bh*S_LEN*DKV;
    const float* Vp = V + (size_t)bh*S_LEN*DKV;

    auto loadKV = [&](int st, int kb){
        float* kd = Ks + st*KS_SZ;
        float* vd = Vs + st*VS_SZ;
        #pragma unroll
        for (int i=0;i<4;i++){
            int idx = tid + 256*i;
            int r = idx >> 4, c = (idx & 15) << 2;
            cp_async16(kd + r*KSTR + c, Kp + (size_t)(kb+r)*DKV + c);
            cp_async16(vd + r*VSTR + c, Vp + (size_t)(kb+r)*DKV + c);
        }
    };

    #pragma unroll
    for (int i=0;i<8;i++){
        int idx = tid + 256*i;
        int r = idx >> 4, c = (idx & 15) << 2;
        cp_async16(Ps + r*PSTR + c, Qp + (size_t)(qb+r)*DKV + c);
    }
    cp_commit();
    loadKV(0, 0);
    cp_commit();
    cp_wait<1>();
    __syncthreads();

    // Q fragments with softmax scale * log2(e) folded in (needs re-round after scale)
    const float sc = 0.125f * 1.4426950408889634f;
    const int r0 = warp*16 + (lane>>2);
    unsigned qf[8][4];
    #pragma unroll
    for (int ks=0; ks<8; ks++){
        const float* p = Ps + r0*PSTR + ks*8 + (lane&3);
        qf[ks][0] = f2tf(p[0] * sc);
        qf[ks][1] = f2tf(p[8*PSTR] * sc);
        qf[ks][2] = f2tf(p[4] * sc);
        qf[ks][3] = f2tf(p[8*PSTR+4] * sc);
    }
    __syncthreads();

    float o[8][4];
    #pragma unroll
    for (int i=0;i<8;i++)
        #pragma unroll
        for (int j=0;j<4;j++) o[i][j]=0.f;
    float m0 = -1e30f, m1 = -1e30f, l0 = 0.f, l1 = 0.f;

    for (int t=0; t<32; t++){
        if (t+1 < 32){ loadKV((t+1)&1, (t+1)*64); cp_commit(); cp_wait<1>(); }
        else           cp_wait<0>();
        __syncthreads();
        const float* ks_ = Ks + (t&1)*KS_SZ;
        const float* vs_ = Vs + (t&1)*VS_SZ;

        // S = (Q*sc) @ K^T : raw bit loads, K pre-rounded
        float s[8][4];
        #pragma unroll
        for (int i=0;i<8;i++)
            #pragma unroll
            for (int j=0;j<4;j++) s[i][j]=0.f;
        #pragma unroll
        for (int kp2=0; kp2<8; kp2++){
            #pragma unroll
            for (int nt=0; nt<8; nt++){
                const float* bp = ks_ + (nt*8 + (lane>>2))*KSTR + kp2*8 + (lane&3);
                unsigned b0 = __float_as_uint(bp[0]);
                unsigned b1 = __float_as_uint(bp[4]);
                mma_tf32(s[nt], qf[kp2], b0, b1);
            }
        }

        // online softmax (log2 domain); P rounded to tf32 BEFORE summation so
        // numerator and denominator use identical weights
        float mx0 = s[0][0], mx1 = s[0][2];
        #pragma unroll
        for (int nt=0; nt<8; nt++){
            mx0 = fmaxf(mx0, fmaxf(s[nt][0], s[nt][1]));
            mx1 = fmaxf(mx1, fmaxf(s[nt][2], s[nt][3]));
        }
        mx0 = fmaxf(mx0, __shfl_xor_sync(0xffffffffu, mx0, 1));
        mx0 = fmaxf(mx0, __shfl_xor_sync(0xffffffffu, mx0, 2));
        mx1 = fmaxf(mx1, __shfl_xor_sync(0xffffffffu, mx1, 1));
        mx1 = fmaxf(mx1, __shfl_xor_sync(0xffffffffu, mx1, 2));
        const float mn0 = fmaxf(m0, mx0), mn1 = fmaxf(m1, mx1);
        const float a0 = ex2(m0 - mn0),   a1 = ex2(m1 - mn1);
        float sum0 = 0.f, sum1 = 0.f;
        #pragma unroll
        for (int nt=0; nt<8; nt++){
            float p0 = rtf(ex2(s[nt][0]-mn0)), p1 = rtf(ex2(s[nt][1]-mn0));
            float p2 = rtf(ex2(s[nt][2]-mn1)), p3 = rtf(ex2(s[nt][3]-mn1));
            sum0 += p0 + p1; sum1 += p2 + p3;
            float* pw = Ps + r0*PSTR + nt*8 + (lane&3)*2;
            *reinterpret_cast<float2*>(pw)          = make_float2(p0, p1);
            *reinterpret_cast<float2*>(pw + 8*PSTR) = make_float2(p2, p3);
        }
        sum0 += __shfl_xor_sync(0xffffffffu, sum0, 1);
        sum0 += __shfl_xor_sync(0xffffffffu, sum0, 2);
        sum1 += __shfl_xor_sync(0xffffffffu, sum1, 1);
        sum1 += __shfl_xor_sync(0xffffffffu, sum1, 2);
        l0 = l0*a0 + sum0; l1 = l1*a1 + sum1;
        m0 = mn0; m1 = mn1;
        #pragma unroll
        for (int nt=0; nt<8; nt++){ o[nt][0]*=a0; o[nt][1]*=a0; o[nt][2]*=a1; o[nt][3]*=a1; }
        __syncwarp();   // P rows are warp-private

        // O += P @ V : raw bit loads, P & V pre-rounded
        #pragma unroll
        for (int kp2=0; kp2<8; kp2++){
            unsigned pa[4];
            const float* pp = Ps + r0*PSTR + kp2*8 + (lane&3);
            pa[0] = __float_as_uint(pp[0]);
            pa[1] = __float_as_uint(pp[8*PSTR]);
            pa[2] = __float_as_uint(pp[4]);
            pa[3] = __float_as_uint(pp[8*PSTR+4]);
            #pragma unroll
            for (int nt=0; nt<8; nt++){
                const float* bp = vs_ + (kp2*8 + (lane&3))*VSTR + nt*8 + (lane>>2);
                unsigned b0 = __float_as_uint(bp[0]);
                unsigned b1 = __float_as_uint(bp[4*VSTR]);
                mma_tf32(o[nt], pa, b0, b1);
            }
        }
        __syncthreads();
    }

    // normalize + write ctx[b, s, h*64+d] pre-rounded to tf32 for gemm<1>
    const float il0 = __fdividef(1.f, l0), il1 = __fdividef(1.f, l1);
    const int b = bh >> 4, h = bh & 15;
    const size_t row0 = ((size_t)b*S_LEN + qb + r0) * HID + h*DKV;
    #pragma unroll
    for (int nt=0; nt<8; nt++){
        const int c = nt*8 + (lane&3)*2;
        *reinterpret_cast<float2*>(ctx + row0 + c) =
            make_float2(rtf(o[nt][0]*il0), rtf(o[nt][1]*il0));
        *reinterpret_cast<float2*>(ctx + row0 + 8*HID + c) =
            make_float2(rtf(o[nt][2]*il1), rtf(o[nt][3]*il1));
    }
}

// ---------------- launch ----------------
extern "C" void kernel_launch(void* const* d_in, const int* in_sizes, int n_in,
                              void* d_out, int out_size)
{
    const float* x  = (const float*)d_in[0];
    const float* W1 = (const float*)d_in[1];
    const float* b1 = (const float*)d_in[2];
    const float* W2 = (const float*)d_in[3];
    const float* b2 = (const float*)d_in[4];
    float* out = (float*)d_out;

    float *qp, *kp, *vp, *cp, *xp, *w1p, *w2p;
    cudaGetSymbolAddress((void**)&qp,  g_q);
    cudaGetSymbolAddress((void**)&kp,  g_k);
    cudaGetSymbolAddress((void**)&vp,  g_v);
    cudaGetSymbolAddress((void**)&cp,  g_ctx);
    cudaGetSymbolAddress((void**)&xp,  g_x);
    cudaGetSymbolAddress((void**)&w1p, g_w1);
    cudaGetSymbolAddress((void**)&w2p, g_w2);

    cudaFuncSetAttribute(gemm_tf32<0>, cudaFuncAttributeMaxDynamicSharedMemorySize, GEMM_SMEM);
    cudaFuncSetAttribute(gemm_tf32<1>, cudaFuncAttributeMaxDynamicSharedMemorySize, GEMM_SMEM);
    cudaFuncSetAttribute(attn_tf32,    cudaFuncAttributeMaxDynamicSharedMemorySize, ATT_SMEM);

    dim3 blk(256);
    // 0) prepass: tf32-round the raw inputs once
    {
        int n4x  = MROWS*HID/4;
        int n4w1 = HID*3*NHEADS*DKV/4;
        int n4w2 = NHEADS*DKV*HID/4;
        round_tf32_kernel<<<(n4x +255)/256, 256>>>(x,  xp,  n4x);
        round_tf32_kernel<<<(n4w1+255)/256, 256>>>(W1, w1p, n4w1);
        round_tf32_kernel<<<(n4w2+255)/256, 256>>>(W2, w2p, n4w2);
    }
    // 1) QKV projection + scatter to [b,h,s,d] (pre-rounded outputs)
    gemm_tf32<0><<<dim3(3*HID/BN, MROWS/BM), blk, GEMM_SMEM>>>(
        xp, w1p, b1, nullptr, 3*HID, HID, qp, kp, vp);
    // 2) flash attention -> ctx [b,s,h*d] (pre-rounded)
    attn_tf32<<<dim3(S_LEN/128, BATCH*NHEADS), blk, ATT_SMEM>>>(qp, kp, vp, cp);
    // 3) output projection (exact fp32 epilogue)
    gemm_tf32<1><<<dim3(HID/BN, MROWS/BM), blk, GEMM_SMEM>>>(
        cp, w2p, b2, out, HID, HID, nullptr, nullptr, nullptr);
}